// round 14
// baseline (speedup 1.0000x reference)
#include <cuda_runtime.h>
#include <cuda_fp16.h>
#include <cstdint>

#define B_      4
#define V_IN    12500
#define V_OUT   50000
#define C_IN    64
#define C_OUT   32
#define SPIRAL  9
#define TILE_V  256
#define NT      128

#define XH_ITEMS  (B_ * V_IN * 16)                     // float4 items (uint2 out)
#define XH_BLOCKS ((XH_ITEMS / 2 + 255) / 256)         // 2 items/thread -> 1563
#define UP_BLOCKS (V_OUT * 32 / 256)                   // 6250
#define WF_BLOCKS ((9 * 4 * 2 * 128 + 255) / 256)      // 36

// ---------------------------------------------------------------------------
// device scratch
// x in fp16: [b][v][64]  (6.4 MB)
__device__ __half g_x_h[(size_t)B_ * V_IN * 64];
// up rows: per (b,v): 64 fp16 = 128 B
__device__ __half g_up_h[(size_t)B_ * V_OUT * 64];
// W in mma B-fragment order: [s][kc][ntpair][lane][4 x b32] = 9*4*2*128 u32
__device__ uint32_t g_wf[9 * 4 * 2 * 128];

// ---------------------------------------------------------------------------
__device__ __forceinline__ uint32_t smem_u32(const void* p) {
    uint32_t a;
    asm("{ .reg .u64 t; cvta.to.shared.u64 t, %1; cvt.u32.u64 %0, t; }"
        : "=r"(a) : "l"(p));
    return a;
}
// L1-bypassing copy for the random-row A gather (no L1 hits possible)
__device__ __forceinline__ void cp16_cg(uint32_t dst, const void* src) {
    asm volatile("cp.async.cg.shared.global [%0], [%1], 16;"
                 :: "r"(dst), "l"(src) : "memory");
}
__device__ __forceinline__ void ldsm4(uint32_t* r, uint32_t addr) {
    asm volatile("ldmatrix.sync.aligned.m8n8.x4.shared.b16 {%0,%1,%2,%3}, [%4];"
                 : "=r"(r[0]), "=r"(r[1]), "=r"(r[2]), "=r"(r[3]) : "r"(addr));
}
__device__ __forceinline__ void mma16816(float* c, const uint32_t* a,
                                         uint32_t b0, uint32_t b1) {
    asm volatile(
        "mma.sync.aligned.m16n8k16.row.col.f32.f16.f16.f32 "
        "{%0,%1,%2,%3},{%4,%5,%6,%7},{%8,%9},{%0,%1,%2,%3};"
        : "+f"(c[0]), "+f"(c[1]), "+f"(c[2]), "+f"(c[3])
        : "r"(a[0]), "r"(a[1]), "r"(a[2]), "r"(a[3]), "r"(b0), "r"(b1));
}
static __device__ __forceinline__ uint32_t pack_h2(float a, float b) {
    __half2 h = __floats2half2_rn(a, b);
    return *reinterpret_cast<uint32_t*>(&h);
}
static __device__ __forceinline__ float2 h2f2(uint32_t u) {
    __half2 h = *reinterpret_cast<__half2*>(&u);
    return __half22float2(h);
}

// ---------------------------------------------------------------------------
// Kernel 0: x (fp32) -> g_x_h (fp16), streaming, 2 items/thread for MLP.
// XH_ITEMS = B*V_IN*16 float4 items (FIX of R13's *8 undercount).
// ---------------------------------------------------------------------------
__global__ void xh_kernel(const float* __restrict__ x) {
    int t0 = blockIdx.x * blockDim.x + threadIdx.x;
#pragma unroll
    for (int it = 0; it < 2; ++it) {
        int t = t0 * 2 + it;
        if (t < XH_ITEMS) {
            float4 f = __ldg((const float4*)x + t);
            uint32_t lo = pack_h2(f.x, f.y);
            uint32_t hi = pack_h2(f.z, f.w);
            ((uint2*)g_x_h)[t] = make_uint2(lo, hi);
        }
    }
}

// ---------------------------------------------------------------------------
// Prep kernel (fused):
//  blocks [0, UP_BLOCKS): up[b,v,c] fp16 from fp16 x (halved gather traffic).
//  blocks [UP_BLOCKS, +WF_BLOCKS): W -> mma B-fragment order (fp16 pairs).
// ---------------------------------------------------------------------------
__global__ void prep_kernel(const int*   __restrict__ up_idx,
                            const float* __restrict__ up_val,
                            const float* __restrict__ weight) {
    if (blockIdx.x >= UP_BLOCKS) {
        int t = (blockIdx.x - UP_BLOCKS) * 256 + threadIdx.x;
        if (t < 9 * 4 * 2 * 128) {
            int s    = t >> 10;            // /1024
            int rem  = t & 1023;
            int kc   = rem >> 8;
            int rem2 = rem & 255;
            int ntp  = rem2 >> 7;
            int j    = rem2 & 127;
            int lane = j >> 2;
            int r    = j & 3;
            int nt8  = ntp * 2 + (r >> 1);
            int pr   = r & 1;
            int n    = nt8 * 8 + (lane >> 2);
            int k    = kc * 16 + pr * 8 + 2 * (lane & 3);
            float f0 = __ldg(weight + (size_t)(s * 64 + k)     * C_OUT + n);
            float f1 = __ldg(weight + (size_t)(s * 64 + k + 1) * C_OUT + n);
            g_wf[t] = pack_h2(f0, f1);
        }
        return;
    }

    int t = blockIdx.x * 256 + threadIdx.x;     // < V_OUT * 32
    int v = t >> 5;
    int b = (t >> 3) & 3;
    int q = t & 7;              // channels 8q..8q+7 (16 B fp16 chunk)

    int   i0 = __ldg(up_idx + v * 3 + 0);
    int   i1 = __ldg(up_idx + v * 3 + 1);
    int   i2 = __ldg(up_idx + v * 3 + 2);
    float w0 = __ldg(up_val + v * 3 + 0);
    float w1 = __ldg(up_val + v * 3 + 1);
    float w2 = __ldg(up_val + v * 3 + 2);

    const uint4* xb = (const uint4*)(g_x_h + (size_t)b * V_IN * 64);
    uint4 ra = __ldg(xb + (size_t)i0 * 8 + q);   // 8 fp16 of row i0
    uint4 rb = __ldg(xb + (size_t)i1 * 8 + q);
    uint4 rc = __ldg(xb + (size_t)i2 * 8 + q);

    uint4 hv;
    {
        float2 a0 = h2f2(ra.x), b0 = h2f2(rb.x), c0 = h2f2(rc.x);
        hv.x = pack_h2(fmaf(a0.x, w0, fmaf(b0.x, w1, c0.x * w2)),
                       fmaf(a0.y, w0, fmaf(b0.y, w1, c0.y * w2)));
        float2 a1 = h2f2(ra.y), b1 = h2f2(rb.y), c1 = h2f2(rc.y);
        hv.y = pack_h2(fmaf(a1.x, w0, fmaf(b1.x, w1, c1.x * w2)),
                       fmaf(a1.y, w0, fmaf(b1.y, w1, c1.y * w2)));
        float2 a2 = h2f2(ra.z), b2 = h2f2(rb.z), c2 = h2f2(rc.z);
        hv.z = pack_h2(fmaf(a2.x, w0, fmaf(b2.x, w1, c2.x * w2)),
                       fmaf(a2.y, w0, fmaf(b2.y, w1, c2.y * w2)));
        float2 a3 = h2f2(ra.w), b3 = h2f2(rb.w), c3 = h2f2(rc.w);
        hv.w = pack_h2(fmaf(a3.x, w0, fmaf(b3.x, w1, c3.x * w2)),
                       fmaf(a3.y, w0, fmaf(b3.y, w1, c3.y * w2)));
    }
    *(uint4*)(g_up_h + (size_t)(b * V_OUT + v) * 64 + q * 8) = hv;
}

// ---------------------------------------------------------------------------
// Main kernel: CTA = 256 vertices x 1 batch, 4 warps, warp tile M=64,N=32.
// 2 CTAs/SM. 3-deep warp-private A ring: gather(s+2) issued at the TOP of
// stage s into buffer (s+2)%3 (free since stage s-1) -> prefetch distance =
// 2 full compute stages -> L2 latency fully hidden. W direct from gmem in
// fragment order (LDG.128, L1-resident). No CTA barrier in the stage loop.
// SMEM: [0,4608)        spiral indices (256 rows x 9, uint16)
//       [4608,102912)   A ring: 3 stages x 32768
// ---------------------------------------------------------------------------
#define OFF_SIDX 0
#define OFF_A    4608
#define SMEM_TOT 102912

__global__ void __launch_bounds__(NT, 2)
spiral_mma_kernel(const int*   __restrict__ spiral,
                  const float* __restrict__ bias,
                  float*       __restrict__ out) {
    extern __shared__ char smem[];
    const uint32_t sb = smem_u32(smem);
    const int tid   = threadIdx.x;
    const int wid   = tid >> 5;
    const int l     = tid & 31;
    const int b     = blockIdx.y;
    const int vbase = blockIdx.x * TILE_V;

    // stage spiral indices for the tile into SMEM (uint16)
    unsigned short* sidx = (unsigned short*)(smem + OFF_SIDX);
#pragma unroll
    for (int i = 0; i < 18; ++i) {
        int j = tid + i * NT;                 // [0, 2304)
        int v = vbase + j / SPIRAL;
        if (v >= V_OUT) v = V_OUT - 1;
        sidx[j] = (unsigned short)__ldg(spiral + (size_t)v * SPIRAL + (j % SPIRAL));
    }
    __syncthreads();   // sidx ready; the ONLY CTA barrier in this kernel

    const char* upb = (const char*)(g_up_h + (size_t)b * V_OUT * 64);
    // warp-private gather: lane l covers chunk gc of rows gr0 + 4j
    const int gc  = l & 7;
    const int gr0 = wid * 64 + (l >> 3);

#define GATHER(s_) do {                                                        \
        uint32_t ab_ = sb + OFF_A + (uint32_t)((s_) % 3) * 32768;              \
        _Pragma("unroll")                                                      \
        for (int j_ = 0; j_ < 16; ++j_) {                                      \
            int row_ = gr0 + 4 * j_;                                           \
            int u_   = (int)sidx[row_ * SPIRAL + (s_)];                        \
            cp16_cg(ab_ + (uint32_t)row_ * 128                                 \
                        + (uint32_t)((gc ^ (row_ & 7)) << 4),                  \
                    upb + (size_t)u_ * 128 + gc * 16);                         \
        }                                                                      \
    } while (0)

    GATHER(0);
    asm volatile("cp.async.commit_group;" ::: "memory");
    GATHER(1);
    asm volatile("cp.async.commit_group;" ::: "memory");

    // per-thread ldmatrix addressing (rows wid*64 + mt*16 + (l&15))
    const uint32_t xk    = (uint32_t)(l & 7);
    const uint32_t a_sel = (uint32_t)(l >> 4);
    const uint32_t a_off = (uint32_t)(wid * 64 + (l & 15)) * 128;

    float acc[4][4][4];
#pragma unroll
    for (int mt = 0; mt < 4; ++mt)
#pragma unroll
        for (int nt = 0; nt < 4; ++nt)
#pragma unroll
            for (int i = 0; i < 4; ++i) acc[mt][nt][i] = 0.f;

    for (int s = 0; s < SPIRAL; ++s) {
        // top-of-stage prefetch: buffer (s+2)%3 was released at stage s-1
        if (s + 2 < SPIRAL) {
            GATHER(s + 2);
            asm volatile("cp.async.commit_group;" ::: "memory");
        }
        // wait for gather(s): groups committed so far = g0..g(min(s+2,8))
        if (s < SPIRAL - 2)       asm volatile("cp.async.wait_group 2;" ::: "memory");
        else if (s == SPIRAL - 2) asm volatile("cp.async.wait_group 1;" ::: "memory");
        else                      asm volatile("cp.async.wait_group 0;" ::: "memory");
        __syncwarp();      // warp-private stage: warp-level visibility suffices

        const uint32_t Ab = sb + OFF_A + (uint32_t)(s % 3) * 32768;
        const uint4* wfs = (const uint4*)(g_wf + (size_t)s * 1024);

#pragma unroll
        for (int kc = 0; kc < 4; ++kc) {
            const uint32_t sa = ((2u * kc + a_sel) ^ xk) << 4;

            uint32_t a[4][4];
#pragma unroll
            for (int mt = 0; mt < 4; ++mt)
                ldsm4(a[mt], Ab + a_off + (uint32_t)mt * 2048 + sa);

            uint4 wA = __ldg(wfs + kc * 64 + l);        // ntpair 0 (nt 0,1)
            uint4 wB = __ldg(wfs + kc * 64 + 32 + l);   // ntpair 1 (nt 2,3)

#pragma unroll
            for (int mt = 0; mt < 4; ++mt) {
                mma16816(acc[mt][0], a[mt], wA.x, wA.y);
                mma16816(acc[mt][1], a[mt], wA.z, wA.w);
                mma16816(acc[mt][2], a[mt], wB.x, wB.y);
                mma16816(acc[mt][3], a[mt], wB.z, wB.w);
            }
        }
    }

    // epilogue: thread owns rows (mt*16 + q, +8), cols r2, r2+1 per n-group
    const int q  = l >> 2;
    const int r2 = (l & 3) * 2;
    float bsv[8];
#pragma unroll
    for (int nt = 0; nt < 4; ++nt) {
        bsv[nt * 2 + 0] = __ldg(bias + nt * 8 + r2);
        bsv[nt * 2 + 1] = __ldg(bias + nt * 8 + r2 + 1);
    }
#pragma unroll
    for (int mt = 0; mt < 4; ++mt)
#pragma unroll
        for (int h2 = 0; h2 < 2; ++h2) {
            int v = vbase + wid * 64 + mt * 16 + q + h2 * 8;
            if (v < V_OUT) {
                float* dst = out + ((size_t)b * V_OUT + v) * C_OUT + r2;
#pragma unroll
                for (int nt = 0; nt < 4; ++nt) {
                    float2 r;
                    r.x = fmaxf(acc[mt][nt][h2 * 2 + 0] + bsv[nt * 2 + 0], 0.f);
                    r.y = fmaxf(acc[mt][nt][h2 * 2 + 1] + bsv[nt * 2 + 1], 0.f);
                    *(float2*)(dst + nt * 8) = r;
                }
            }
        }
#undef GATHER
}

// ---------------------------------------------------------------------------
extern "C" void kernel_launch(void* const* d_in, const int* in_sizes, int n_in,
                              void* d_out, int out_size) {
    const float* x      = (const float*)d_in[0];
    const int*   spiral = (const int*)  d_in[1];
    const int*   up_idx = (const int*)  d_in[2];
    const float* up_val = (const float*)d_in[3];
    const float* weight = (const float*)d_in[4];
    const float* bias   = (const float*)d_in[5];
    float*       out    = (float*)d_out;

    xh_kernel<<<XH_BLOCKS, 256>>>(x);
    prep_kernel<<<UP_BLOCKS + WF_BLOCKS, 256>>>(up_idx, up_val, weight);

    cudaFuncSetAttribute(spiral_mma_kernel,
                         cudaFuncAttributeMaxDynamicSharedMemorySize, SMEM_TOT);
    dim3 grid((V_OUT + TILE_V - 1) / TILE_V, B_);
    spiral_mma_kernel<<<grid, NT, SMEM_TOT>>>(spiral, bias, out);
}

// round 15
// speedup vs baseline: 1.1432x; 1.1432x over previous
#include <cuda_runtime.h>
#include <cuda_fp16.h>
#include <cstdint>

#define B_      4
#define V_IN    12500
#define V_OUT   50000
#define C_IN    64
#define C_OUT   32
#define SPIRAL  9
#define TILE_V  256
#define NT      128

#define XH_ITEMS  (B_ * V_IN * 16)                     // float4 items
#define XH_BLOCKS ((XH_ITEMS / 4 + 255) / 256)         // 4 items/thread -> 782
#define UP_BLOCKS (V_OUT * 32 / 256)                   // 6250
#define WF_BLOCKS ((9 * 4 * 2 * 128 + 255) / 256)      // 36

// ---------------------------------------------------------------------------
// device scratch
// x in fp16: [b][v][64]  (6.4 MB)
__device__ __half g_x_h[(size_t)B_ * V_IN * 64];
// up rows: per (b,v): 64 fp16 = 128 B
__device__ __half g_up_h[(size_t)B_ * V_OUT * 64];
// W in mma B-fragment order: [s][kc][ntpair][lane][4 x b32] = 9*4*2*128 u32
__device__ uint32_t g_wf[9 * 4 * 2 * 128];

// ---------------------------------------------------------------------------
__device__ __forceinline__ uint32_t smem_u32(const void* p) {
    uint32_t a;
    asm("{ .reg .u64 t; cvta.to.shared.u64 t, %1; cvt.u32.u64 %0, t; }"
        : "=r"(a) : "l"(p));
    return a;
}
// L1-bypassing copy for the random-row A gather (no L1 hits possible)
__device__ __forceinline__ void cp16_cg(uint32_t dst, const void* src) {
    asm volatile("cp.async.cg.shared.global [%0], [%1], 16;"
                 :: "r"(dst), "l"(src) : "memory");
}
__device__ __forceinline__ void ldsm4(uint32_t* r, uint32_t addr) {
    asm volatile("ldmatrix.sync.aligned.m8n8.x4.shared.b16 {%0,%1,%2,%3}, [%4];"
                 : "=r"(r[0]), "=r"(r[1]), "=r"(r[2]), "=r"(r[3]) : "r"(addr));
}
__device__ __forceinline__ void mma16816(float* c, const uint32_t* a,
                                         uint32_t b0, uint32_t b1) {
    asm volatile(
        "mma.sync.aligned.m16n8k16.row.col.f32.f16.f16.f32 "
        "{%0,%1,%2,%3},{%4,%5,%6,%7},{%8,%9},{%0,%1,%2,%3};"
        : "+f"(c[0]), "+f"(c[1]), "+f"(c[2]), "+f"(c[3])
        : "r"(a[0]), "r"(a[1]), "r"(a[2]), "r"(a[3]), "r"(b0), "r"(b1));
}
static __device__ __forceinline__ uint32_t pack_h2(float a, float b) {
    __half2 h = __floats2half2_rn(a, b);
    return *reinterpret_cast<uint32_t*>(&h);
}
static __device__ __forceinline__ float2 h2f2(uint32_t u) {
    __half2 h = *reinterpret_cast<__half2*>(&u);
    return __half22float2(h);
}

// ---------------------------------------------------------------------------
// Kernel 0: x (fp32) -> g_x_h (fp16). 4 independent float4 items per thread
// (strided by blockDim) for MLP=4; removes the DRAM-latency exposure.
// ---------------------------------------------------------------------------
__global__ void xh_kernel(const float* __restrict__ x) {
    int base = blockIdx.x * 1024 + threadIdx.x;
#pragma unroll
    for (int it = 0; it < 4; ++it) {
        int t = base + it * 256;
        if (t < XH_ITEMS) {
            float4 f = __ldg((const float4*)x + t);
            uint32_t lo = pack_h2(f.x, f.y);
            uint32_t hi = pack_h2(f.z, f.w);
            ((uint2*)g_x_h)[t] = make_uint2(lo, hi);
        }
    }
}

// ---------------------------------------------------------------------------
// Prep kernel (fused):
//  blocks [0, UP_BLOCKS): up[b,v,c] fp16 from fp16 x (halved gather traffic).
//  blocks [UP_BLOCKS, +WF_BLOCKS): W -> mma B-fragment order (fp16 pairs).
// ---------------------------------------------------------------------------
__global__ void prep_kernel(const int*   __restrict__ up_idx,
                            const float* __restrict__ up_val,
                            const float* __restrict__ weight) {
    if (blockIdx.x >= UP_BLOCKS) {
        int t = (blockIdx.x - UP_BLOCKS) * 256 + threadIdx.x;
        if (t < 9 * 4 * 2 * 128) {
            int s    = t >> 10;            // /1024
            int rem  = t & 1023;
            int kc   = rem >> 8;
            int rem2 = rem & 255;
            int ntp  = rem2 >> 7;
            int j    = rem2 & 127;
            int lane = j >> 2;
            int r    = j & 3;
            int nt8  = ntp * 2 + (r >> 1);
            int pr   = r & 1;
            int n    = nt8 * 8 + (lane >> 2);
            int k    = kc * 16 + pr * 8 + 2 * (lane & 3);
            float f0 = __ldg(weight + (size_t)(s * 64 + k)     * C_OUT + n);
            float f1 = __ldg(weight + (size_t)(s * 64 + k + 1) * C_OUT + n);
            g_wf[t] = pack_h2(f0, f1);
        }
        return;
    }

    int t = blockIdx.x * 256 + threadIdx.x;     // < V_OUT * 32
    int v = t >> 5;
    int b = (t >> 3) & 3;
    int q = t & 7;              // channels 8q..8q+7 (16 B fp16 chunk)

    int   i0 = __ldg(up_idx + v * 3 + 0);
    int   i1 = __ldg(up_idx + v * 3 + 1);
    int   i2 = __ldg(up_idx + v * 3 + 2);
    float w0 = __ldg(up_val + v * 3 + 0);
    float w1 = __ldg(up_val + v * 3 + 1);
    float w2 = __ldg(up_val + v * 3 + 2);

    const uint4* xb = (const uint4*)(g_x_h + (size_t)b * V_IN * 64);
    uint4 ra = __ldg(xb + (size_t)i0 * 8 + q);   // 8 fp16 of row i0
    uint4 rb = __ldg(xb + (size_t)i1 * 8 + q);
    uint4 rc = __ldg(xb + (size_t)i2 * 8 + q);

    uint4 hv;
    {
        float2 a0 = h2f2(ra.x), b0 = h2f2(rb.x), c0 = h2f2(rc.x);
        hv.x = pack_h2(fmaf(a0.x, w0, fmaf(b0.x, w1, c0.x * w2)),
                       fmaf(a0.y, w0, fmaf(b0.y, w1, c0.y * w2)));
        float2 a1 = h2f2(ra.y), b1 = h2f2(rb.y), c1 = h2f2(rc.y);
        hv.y = pack_h2(fmaf(a1.x, w0, fmaf(b1.x, w1, c1.x * w2)),
                       fmaf(a1.y, w0, fmaf(b1.y, w1, c1.y * w2)));
        float2 a2 = h2f2(ra.z), b2 = h2f2(rb.z), c2 = h2f2(rc.z);
        hv.z = pack_h2(fmaf(a2.x, w0, fmaf(b2.x, w1, c2.x * w2)),
                       fmaf(a2.y, w0, fmaf(b2.y, w1, c2.y * w2)));
        float2 a3 = h2f2(ra.w), b3 = h2f2(rb.w), c3 = h2f2(rc.w);
        hv.w = pack_h2(fmaf(a3.x, w0, fmaf(b3.x, w1, c3.x * w2)),
                       fmaf(a3.y, w0, fmaf(b3.y, w1, c3.y * w2)));
    }
    *(uint4*)(g_up_h + (size_t)(b * V_OUT + v) * 64 + q * 8) = hv;
}

// ---------------------------------------------------------------------------
// Main kernel (R12 best config, unchanged): CTA = 256 vertices x 1 batch,
// 4 warps, warp tile M=64,N=32, 3 CTAs/SM, 2-deep warp-private A ring
// (cp.async.cg), W direct from gmem in fragment order (LDG.128, L1-resident),
// no CTA barrier in the stage loop.
// SMEM: [0,4608)       spiral indices (256 rows x 9, uint16)
//       [4608,70144)   A ring: 2 stages x 32768
// ---------------------------------------------------------------------------
#define OFF_SIDX 0
#define OFF_A    4608
#define SMEM_TOT 70144

__global__ void __launch_bounds__(NT, 3)
spiral_mma_kernel(const int*   __restrict__ spiral,
                  const float* __restrict__ bias,
                  float*       __restrict__ out) {
    extern __shared__ char smem[];
    const uint32_t sb = smem_u32(smem);
    const int tid   = threadIdx.x;
    const int wid   = tid >> 5;
    const int l     = tid & 31;
    const int b     = blockIdx.y;
    const int vbase = blockIdx.x * TILE_V;

    // stage spiral indices for the tile into SMEM (uint16)
    unsigned short* sidx = (unsigned short*)(smem + OFF_SIDX);
#pragma unroll
    for (int i = 0; i < 18; ++i) {
        int j = tid + i * NT;                 // [0, 2304)
        int v = vbase + j / SPIRAL;
        if (v >= V_OUT) v = V_OUT - 1;
        sidx[j] = (unsigned short)__ldg(spiral + (size_t)v * SPIRAL + (j % SPIRAL));
    }
    __syncthreads();   // sidx ready; the ONLY CTA barrier in this kernel

    const char* upb = (const char*)(g_up_h + (size_t)b * V_OUT * 64);
    // warp-private gather: lane l covers chunk gc of rows gr0 + 4j
    const int gc  = l & 7;
    const int gr0 = wid * 64 + (l >> 3);

#define GATHER(s_) do {                                                        \
        uint32_t ab_ = sb + OFF_A + (uint32_t)((s_) & 1) * 32768;              \
        _Pragma("unroll")                                                      \
        for (int j_ = 0; j_ < 16; ++j_) {                                      \
            int row_ = gr0 + 4 * j_;                                           \
            int u_   = (int)sidx[row_ * SPIRAL + (s_)];                        \
            cp16_cg(ab_ + (uint32_t)row_ * 128                                 \
                        + (uint32_t)((gc ^ (row_ & 7)) << 4),                  \
                    upb + (size_t)u_ * 128 + gc * 16);                         \
        }                                                                      \
    } while (0)

    GATHER(0);
    asm volatile("cp.async.commit_group;" ::: "memory");
    GATHER(1);
    asm volatile("cp.async.commit_group;" ::: "memory");

    // per-thread ldmatrix addressing (rows wid*64 + mt*16 + (l&15))
    const uint32_t xk    = (uint32_t)(l & 7);
    const uint32_t a_sel = (uint32_t)(l >> 4);
    const uint32_t a_off = (uint32_t)(wid * 64 + (l & 15)) * 128;

    float acc[4][4][4];
#pragma unroll
    for (int mt = 0; mt < 4; ++mt)
#pragma unroll
        for (int nt = 0; nt < 4; ++nt)
#pragma unroll
            for (int i = 0; i < 4; ++i) acc[mt][nt][i] = 0.f;

    for (int s = 0; s < SPIRAL; ++s) {
        if (s < SPIRAL - 1) asm volatile("cp.async.wait_group 1;" ::: "memory");
        else                asm volatile("cp.async.wait_group 0;" ::: "memory");
        __syncwarp();      // warp-private stage: warp-level visibility suffices

        const uint32_t Ab = sb + OFF_A + (uint32_t)(s & 1) * 32768;
        const uint4* wfs = (const uint4*)(g_wf + (size_t)s * 1024);

#pragma unroll
        for (int kc = 0; kc < 4; ++kc) {
            const uint32_t sa = ((2u * kc + a_sel) ^ xk) << 4;

            uint32_t a[4][4];
#pragma unroll
            for (int mt = 0; mt < 4; ++mt)
                ldsm4(a[mt], Ab + a_off + (uint32_t)mt * 2048 + sa);

            uint4 wA = __ldg(wfs + kc * 64 + l);        // ntpair 0 (nt 0,1)
            uint4 wB = __ldg(wfs + kc * 64 + 32 + l);   // ntpair 1 (nt 2,3)

#pragma unroll
            for (int mt = 0; mt < 4; ++mt) {
                mma16816(acc[mt][0], a[mt], wA.x, wA.y);
                mma16816(acc[mt][1], a[mt], wA.z, wA.w);
                mma16816(acc[mt][2], a[mt], wB.x, wB.y);
                mma16816(acc[mt][3], a[mt], wB.z, wB.w);
            }
        }

        // warp finished reading its own A[s&1] rows -> safe to refill
        if (s < SPIRAL - 2) {
            GATHER(s + 2);
            asm volatile("cp.async.commit_group;" ::: "memory");
        }
    }

    // epilogue: thread owns rows (mt*16 + q, +8), cols r2, r2+1 per n-group
    const int q  = l >> 2;
    const int r2 = (l & 3) * 2;
    float bsv[8];
#pragma unroll
    for (int nt = 0; nt < 4; ++nt) {
        bsv[nt * 2 + 0] = __ldg(bias + nt * 8 + r2);
        bsv[nt * 2 + 1] = __ldg(bias + nt * 8 + r2 + 1);
    }
#pragma unroll
    for (int mt = 0; mt < 4; ++mt)
#pragma unroll
        for (int h2 = 0; h2 < 2; ++h2) {
            int v = vbase + wid * 64 + mt * 16 + q + h2 * 8;
            if (v < V_OUT) {
                float* dst = out + ((size_t)b * V_OUT + v) * C_OUT + r2;
#pragma unroll
                for (int nt = 0; nt < 4; ++nt) {
                    float2 r;
                    r.x = fmaxf(acc[mt][nt][h2 * 2 + 0] + bsv[nt * 2 + 0], 0.f);
                    r.y = fmaxf(acc[mt][nt][h2 * 2 + 1] + bsv[nt * 2 + 1], 0.f);
                    *(float2*)(dst + nt * 8) = r;
                }
            }
        }
#undef GATHER
}

// ---------------------------------------------------------------------------
extern "C" void kernel_launch(void* const* d_in, const int* in_sizes, int n_in,
                              void* d_out, int out_size) {
    const float* x      = (const float*)d_in[0];
    const int*   spiral = (const int*)  d_in[1];
    const int*   up_idx = (const int*)  d_in[2];
    const float* up_val = (const float*)d_in[3];
    const float* weight = (const float*)d_in[4];
    const float* bias   = (const float*)d_in[5];
    float*       out    = (float*)d_out;

    xh_kernel<<<XH_BLOCKS, 256>>>(x);
    prep_kernel<<<UP_BLOCKS + WF_BLOCKS, 256>>>(up_idx, up_val, weight);

    cudaFuncSetAttribute(spiral_mma_kernel,
                         cudaFuncAttributeMaxDynamicSharedMemorySize, SMEM_TOT);
    dim3 grid((V_OUT + TILE_V - 1) / TILE_V, B_);
    spiral_mma_kernel<<<grid, NT, SMEM_TOT>>>(spiral, bias, out);
}

// round 16
// speedup vs baseline: 1.1947x; 1.0450x over previous
#include <cuda_runtime.h>
#include <cuda_fp16.h>
#include <cstdint>

#define B_      4
#define V_IN    12500
#define V_OUT   50000
#define C_IN    64
#define C_OUT   32
#define SPIRAL  9
#define TILE_V  256
#define NT      128

#define XH_ITEMS  (B_ * V_IN * 16)                     // float4 items
#define XH_BLOCKS ((XH_ITEMS / 4 + 255) / 256)         // 4 items/thread -> 782
#define UP_BLOCKS (V_OUT * 32 / 256)                   // 6250
#define WF_BLOCKS ((9 * 4 * 2 * 128 + 255) / 256)      // 36

// ---------------------------------------------------------------------------
// device scratch
__device__ __half g_x_h[(size_t)B_ * V_IN * 64];        // x fp16 (6.4 MB)
__device__ __half g_up_h[(size_t)B_ * V_OUT * 64];      // up rows, 128 B each
__device__ uint32_t g_wf[9 * 4 * 2 * 128];              // W in B-fragment order

// ---------------------------------------------------------------------------
__device__ __forceinline__ uint32_t smem_u32(const void* p) {
    uint32_t a;
    asm("{ .reg .u64 t; cvta.to.shared.u64 t, %1; cvt.u32.u64 %0, t; }"
        : "=r"(a) : "l"(p));
    return a;
}
__device__ __forceinline__ void cp16_cg(uint32_t dst, const void* src) {
    asm volatile("cp.async.cg.shared.global [%0], [%1], 16;"
                 :: "r"(dst), "l"(src) : "memory");
}
__device__ __forceinline__ void ldsm4(uint32_t* r, uint32_t addr) {
    asm volatile("ldmatrix.sync.aligned.m8n8.x4.shared.b16 {%0,%1,%2,%3}, [%4];"
                 : "=r"(r[0]), "=r"(r[1]), "=r"(r[2]), "=r"(r[3]) : "r"(addr));
}
__device__ __forceinline__ void mma16816(float* c, const uint32_t* a,
                                         uint32_t b0, uint32_t b1) {
    asm volatile(
        "mma.sync.aligned.m16n8k16.row.col.f32.f16.f16.f32 "
        "{%0,%1,%2,%3},{%4,%5,%6,%7},{%8,%9},{%0,%1,%2,%3};"
        : "+f"(c[0]), "+f"(c[1]), "+f"(c[2]), "+f"(c[3])
        : "r"(a[0]), "r"(a[1]), "r"(a[2]), "r"(a[3]), "r"(b0), "r"(b1));
}
static __device__ __forceinline__ uint32_t pack_h2(float a, float b) {
    __half2 h = __floats2half2_rn(a, b);
    return *reinterpret_cast<uint32_t*>(&h);
}
static __device__ __forceinline__ float2 h2f2(uint32_t u) {
    __half2 h = *reinterpret_cast<__half2*>(&u);
    return __half22float2(h);
}

// ---------------------------------------------------------------------------
// Kernel 0: x (fp32) -> g_x_h (fp16), streaming, 4 items/thread
// ---------------------------------------------------------------------------
__global__ void xh_kernel(const float* __restrict__ x) {
    int base = blockIdx.x * 1024 + threadIdx.x;
#pragma unroll
    for (int it = 0; it < 4; ++it) {
        int t = base + it * 256;
        if (t < XH_ITEMS) {
            float4 f = __ldg((const float4*)x + t);
            uint32_t lo = pack_h2(f.x, f.y);
            uint32_t hi = pack_h2(f.z, f.w);
            ((uint2*)g_x_h)[t] = make_uint2(lo, hi);
        }
    }
}

// ---------------------------------------------------------------------------
// Prep kernel (fused): up from fp16 x + W fragment reorder
// ---------------------------------------------------------------------------
__global__ void prep_kernel(const int*   __restrict__ up_idx,
                            const float* __restrict__ up_val,
                            const float* __restrict__ weight) {
    if (blockIdx.x >= UP_BLOCKS) {
        int t = (blockIdx.x - UP_BLOCKS) * 256 + threadIdx.x;
        if (t < 9 * 4 * 2 * 128) {
            int s    = t >> 10;
            int rem  = t & 1023;
            int kc   = rem >> 8;
            int rem2 = rem & 255;
            int ntp  = rem2 >> 7;
            int j    = rem2 & 127;
            int lane = j >> 2;
            int r    = j & 3;
            int nt8  = ntp * 2 + (r >> 1);
            int pr   = r & 1;
            int n    = nt8 * 8 + (lane >> 2);
            int k    = kc * 16 + pr * 8 + 2 * (lane & 3);
            float f0 = __ldg(weight + (size_t)(s * 64 + k)     * C_OUT + n);
            float f1 = __ldg(weight + (size_t)(s * 64 + k + 1) * C_OUT + n);
            g_wf[t] = pack_h2(f0, f1);
        }
        return;
    }

    int t = blockIdx.x * 256 + threadIdx.x;     // < V_OUT * 32
    int v = t >> 5;
    int b = (t >> 3) & 3;
    int q = t & 7;

    int   i0 = __ldg(up_idx + v * 3 + 0);
    int   i1 = __ldg(up_idx + v * 3 + 1);
    int   i2 = __ldg(up_idx + v * 3 + 2);
    float w0 = __ldg(up_val + v * 3 + 0);
    float w1 = __ldg(up_val + v * 3 + 1);
    float w2 = __ldg(up_val + v * 3 + 2);

    const uint4* xb = (const uint4*)(g_x_h + (size_t)b * V_IN * 64);
    uint4 ra = __ldg(xb + (size_t)i0 * 8 + q);
    uint4 rb = __ldg(xb + (size_t)i1 * 8 + q);
    uint4 rc = __ldg(xb + (size_t)i2 * 8 + q);

    uint4 hv;
    {
        float2 a0 = h2f2(ra.x), b0 = h2f2(rb.x), c0 = h2f2(rc.x);
        hv.x = pack_h2(fmaf(a0.x, w0, fmaf(b0.x, w1, c0.x * w2)),
                       fmaf(a0.y, w0, fmaf(b0.y, w1, c0.y * w2)));
        float2 a1 = h2f2(ra.y), b1 = h2f2(rb.y), c1 = h2f2(rc.y);
        hv.y = pack_h2(fmaf(a1.x, w0, fmaf(b1.x, w1, c1.x * w2)),
                       fmaf(a1.y, w0, fmaf(b1.y, w1, c1.y * w2)));
        float2 a2 = h2f2(ra.z), b2 = h2f2(rb.z), c2 = h2f2(rc.z);
        hv.z = pack_h2(fmaf(a2.x, w0, fmaf(b2.x, w1, c2.x * w2)),
                       fmaf(a2.y, w0, fmaf(b2.y, w1, c2.y * w2)));
        float2 a3 = h2f2(ra.w), b3 = h2f2(rb.w), c3 = h2f2(rc.w);
        hv.w = pack_h2(fmaf(a3.x, w0, fmaf(b3.x, w1, c3.x * w2)),
                       fmaf(a3.y, w0, fmaf(b3.y, w1, c3.y * w2)));
    }
    *(uint4*)(g_up_h + (size_t)(b * V_OUT + v) * 64 + q * 8) = hv;
}

// ---------------------------------------------------------------------------
// Main kernel (R12 config, s-loop FULLY UNROLLED): CTA = 256 v x 1 batch,
// 4 warps, warp tile M=64,N=32, 3 CTAs/SM, 2-deep warp-private A ring,
// W via LDG.128 fragments (L1-resident), no CTA barrier in the stage loop.
// SMEM: [0,4608) sidx uint16; [4608,70144) A ring 2 x 32768.
// ---------------------------------------------------------------------------
#define OFF_SIDX 0
#define OFF_A    4608
#define SMEM_TOT 70144

__global__ void __launch_bounds__(NT, 3)
spiral_mma_kernel(const int*   __restrict__ spiral,
                  const float* __restrict__ bias,
                  float*       __restrict__ out) {
    extern __shared__ char smem[];
    const uint32_t sb = smem_u32(smem);
    const int tid   = threadIdx.x;
    const int wid   = tid >> 5;
    const int l     = tid & 31;
    const int b     = blockIdx.y;
    const int vbase = blockIdx.x * TILE_V;

    unsigned short* sidx = (unsigned short*)(smem + OFF_SIDX);
#pragma unroll
    for (int i = 0; i < 18; ++i) {
        int j = tid + i * NT;
        int v = vbase + j / SPIRAL;
        if (v >= V_OUT) v = V_OUT - 1;
        sidx[j] = (unsigned short)__ldg(spiral + (size_t)v * SPIRAL + (j % SPIRAL));
    }
    __syncthreads();   // sidx ready; the ONLY CTA barrier in this kernel

    const char* upb = (const char*)(g_up_h + (size_t)b * V_OUT * 64);
    const int gc  = l & 7;
    const int gr0 = wid * 64 + (l >> 3);

#define GATHER(s_) do {                                                        \
        uint32_t ab_ = sb + OFF_A + (uint32_t)((s_) & 1) * 32768;              \
        _Pragma("unroll")                                                      \
        for (int j_ = 0; j_ < 16; ++j_) {                                      \
            int row_ = gr0 + 4 * j_;                                           \
            int u_   = (int)sidx[row_ * SPIRAL + (s_)];                        \
            cp16_cg(ab_ + (uint32_t)row_ * 128                                 \
                        + (uint32_t)((gc ^ (row_ & 7)) << 4),                  \
                    upb + (size_t)u_ * 128 + gc * 16);                         \
        }                                                                      \
    } while (0)

    GATHER(0);
    asm volatile("cp.async.commit_group;" ::: "memory");
    GATHER(1);
    asm volatile("cp.async.commit_group;" ::: "memory");

    const uint32_t xk    = (uint32_t)(l & 7);
    const uint32_t a_sel = (uint32_t)(l >> 4);
    const uint32_t a_off = (uint32_t)(wid * 64 + (l & 15)) * 128;

    float acc[4][4][4];
#pragma unroll
    for (int mt = 0; mt < 4; ++mt)
#pragma unroll
        for (int nt = 0; nt < 4; ++nt)
#pragma unroll
            for (int i = 0; i < 4; ++i) acc[mt][nt][i] = 0.f;

#pragma unroll
    for (int s = 0; s < SPIRAL; ++s) {
        if (s < SPIRAL - 1) asm volatile("cp.async.wait_group 1;" ::: "memory");
        else                asm volatile("cp.async.wait_group 0;" ::: "memory");
        __syncwarp();

        const uint32_t Ab = sb + OFF_A + (uint32_t)(s & 1) * 32768;
        const uint4* wfs = (const uint4*)(g_wf + (size_t)s * 1024);

#pragma unroll
        for (int kc = 0; kc < 4; ++kc) {
            const uint32_t sa = ((2u * kc + a_sel) ^ xk) << 4;

            uint32_t a[4][4];
#pragma unroll
            for (int mt = 0; mt < 4; ++mt)
                ldsm4(a[mt], Ab + a_off + (uint32_t)mt * 2048 + sa);

            uint4 wA = __ldg(wfs + kc * 64 + l);
            uint4 wB = __ldg(wfs + kc * 64 + 32 + l);

#pragma unroll
            for (int mt = 0; mt < 4; ++mt) {
                mma16816(acc[mt][0], a[mt], wA.x, wA.y);
                mma16816(acc[mt][1], a[mt], wA.z, wA.w);
                mma16816(acc[mt][2], a[mt], wB.x, wB.y);
                mma16816(acc[mt][3], a[mt], wB.z, wB.w);
            }
        }

        // warp finished reading its own A[s&1] rows -> safe to refill
        if (s < SPIRAL - 2) {
            GATHER(s + 2);
            asm volatile("cp.async.commit_group;" ::: "memory");
        }
    }

    // epilogue: streaming stores (out is never re-read; keep L2 for up)
    const int q  = l >> 2;
    const int r2 = (l & 3) * 2;
    float bsv[8];
#pragma unroll
    for (int nt = 0; nt < 4; ++nt) {
        bsv[nt * 2 + 0] = __ldg(bias + nt * 8 + r2);
        bsv[nt * 2 + 1] = __ldg(bias + nt * 8 + r2 + 1);
    }
#pragma unroll
    for (int mt = 0; mt < 4; ++mt)
#pragma unroll
        for (int h2 = 0; h2 < 2; ++h2) {
            int v = vbase + wid * 64 + mt * 16 + q + h2 * 8;
            if (v < V_OUT) {
                float* dst = out + ((size_t)b * V_OUT + v) * C_OUT + r2;
#pragma unroll
                for (int nt = 0; nt < 4; ++nt) {
                    float2 r;
                    r.x = fmaxf(acc[mt][nt][h2 * 2 + 0] + bsv[nt * 2 + 0], 0.f);
                    r.y = fmaxf(acc[mt][nt][h2 * 2 + 1] + bsv[nt * 2 + 1], 0.f);
                    __stcs((float2*)(dst + nt * 8), r);
                }
            }
        }
#undef GATHER
}

// ---------------------------------------------------------------------------
extern "C" void kernel_launch(void* const* d_in, const int* in_sizes, int n_in,
                              void* d_out, int out_size) {
    const float* x      = (const float*)d_in[0];
    const int*   spiral = (const int*)  d_in[1];
    const int*   up_idx = (const int*)  d_in[2];
    const float* up_val = (const float*)d_in[3];
    const float* weight = (const float*)d_in[4];
    const float* bias   = (const float*)d_in[5];
    float*       out    = (float*)d_out;

    xh_kernel<<<XH_BLOCKS, 256>>>(x);
    prep_kernel<<<UP_BLOCKS + WF_BLOCKS, 256>>>(up_idx, up_val, weight);

    cudaFuncSetAttribute(spiral_mma_kernel,
                         cudaFuncAttributeMaxDynamicSharedMemorySize, SMEM_TOT);
    dim3 grid((V_OUT + TILE_V - 1) / TILE_V, B_);
    spiral_mma_kernel<<<grid, NT, SMEM_TOT>>>(spiral, bias, out);
}